// round 6
// baseline (speedup 1.0000x reference)
#include <cuda_runtime.h>

#define Bb 2
#define Ss 2048
#define Dd 512
#define Hh 8
#define DHh 64
#define CAPS 128     // candidate cap per row (expected ~40)

// Scratch (device globals: no runtime allocation allowed)
__device__ float          g_Q[Bb * Hh * Ss * DHh];       // [B,H,S,dh]  8 MB
__device__ float          g_K[Bb * Hh * Ss * DHh];       // [B,H,S,dh]  8 MB
__device__ float          g_V[Bb * Ss * DHh];            // [B,S,dh]    1 MB
__device__ float          g_heads[Bb * Ss * Dd];         // [B,S,D]     8 MB
__device__ unsigned short g_cand[Bb * Hh * Ss * CAPS];   // cand indices 8 MB
__device__ int            g_ccnt[Bb * Hh * Ss];          // cand counts
__device__ float          g_rmax[Bb * Hh * Ss];          // tf32 row maxes

// monotone float<->unsigned encoding for atomicMax on floats
__device__ __forceinline__ unsigned enc_f(float f) {
    unsigned b = __float_as_uint(f);
    return (f >= 0.0f) ? (b | 0x80000000u) : ~b;
}
__device__ __forceinline__ float dec_f(unsigned u) {
    return (u & 0x80000000u) ? __uint_as_float(u & 0x7fffffffu)
                             : __uint_as_float(~u);
}

// ---------------------------------------------------------------------------
// fp32 SGEMM (projections / output): C = A (MxK) * B (KxN or NxK) + bias
// ---------------------------------------------------------------------------
__global__ __launch_bounds__(256) void sgemm_128x64(
    const float* __restrict__ A, int lda, long sA,
    const float* __restrict__ Bmat, int ldb, long sB, int transB,
    const float* __restrict__ bias,
    float* __restrict__ C, int ldc, long sC, int headMajorC,
    int Kdim)
{
    const int BM = 128, BN = 64, BK = 16;
    __shared__ float As[BK][BM + 4];
    __shared__ float Bs[BK][BN + 4];

    const float* Ab = A + (long)blockIdx.z * sA;
    const float* Bp = Bmat + (long)blockIdx.z * sB;
    float* Cb = C + (long)blockIdx.z * sC;

    int tid = threadIdx.x;
    int tx = tid & 15;
    int ty = tid >> 4;
    int m0 = blockIdx.x * BM;
    int n0 = blockIdx.y * BN;

    int ar = tid >> 1;
    int ac = (tid & 1) * 8;
    int br_n = tid >> 2;
    int bc_k = (tid & 3) * 4;
    int br_k = tid >> 4;
    int bc_n = (tid & 15) * 4;

    float acc[8][4];
#pragma unroll
    for (int i = 0; i < 8; ++i)
#pragma unroll
        for (int j = 0; j < 4; ++j) acc[i][j] = 0.0f;

    for (int k0 = 0; k0 < Kdim; k0 += BK) {
        {
            const float* ap = Ab + (long)(m0 + ar) * lda + k0 + ac;
            float4 v0 = *(const float4*)(ap);
            float4 v1 = *(const float4*)(ap + 4);
            As[ac + 0][ar] = v0.x; As[ac + 1][ar] = v0.y;
            As[ac + 2][ar] = v0.z; As[ac + 3][ar] = v0.w;
            As[ac + 4][ar] = v1.x; As[ac + 5][ar] = v1.y;
            As[ac + 6][ar] = v1.z; As[ac + 7][ar] = v1.w;
        }
        if (transB) {
            float4 v = *(const float4*)(Bp + (long)(n0 + br_n) * ldb + k0 + bc_k);
            Bs[bc_k + 0][br_n] = v.x; Bs[bc_k + 1][br_n] = v.y;
            Bs[bc_k + 2][br_n] = v.z; Bs[bc_k + 3][br_n] = v.w;
        } else {
            float4 v = *(const float4*)(Bp + (long)(k0 + br_k) * ldb + n0 + bc_n);
            *(float4*)&Bs[br_k][bc_n] = v;
        }
        __syncthreads();

#pragma unroll
        for (int k = 0; k < BK; ++k) {
            float a[8], b[4];
            *(float4*)&a[0] = *(const float4*)&As[k][ty * 8];
            *(float4*)&a[4] = *(const float4*)&As[k][ty * 8 + 4];
            *(float4*)&b[0] = *(const float4*)&Bs[k][tx * 4];
#pragma unroll
            for (int i = 0; i < 8; ++i)
#pragma unroll
                for (int j = 0; j < 4; ++j)
                    acc[i][j] += a[i] * b[j];
        }
        __syncthreads();
    }

    float4 bv = make_float4(0.f, 0.f, 0.f, 0.f);
    if (bias) bv = *(const float4*)(bias + n0 + tx * 4);

#pragma unroll
    for (int i = 0; i < 8; ++i) {
        int m = m0 + ty * 8 + i;
        float4 o;
        o.x = acc[i][0] + bv.x;
        o.y = acc[i][1] + bv.y;
        o.z = acc[i][2] + bv.z;
        o.w = acc[i][3] + bv.w;
        long addr;
        if (headMajorC) {
            int bb = m >> 11;
            int ss = m & 2047;
            int hh = n0 >> 6;
            addr = ((((long)bb * Hh + hh) * Ss) + ss) * DHh + tx * 4;
        } else {
            addr = (long)m * ldc + n0 + tx * 4;
        }
        *(float4*)(Cb + addr) = o;
    }
}

// ---------------------------------------------------------------------------
// Fused QK + screening: never materializes logits.
// CTA = (q-tile of 128, bh). Streams 16 K-tiles via tf32 mma; keeps a running
// per-row max (encoded atomicMax, deterministic) and appends candidate key
// indices {z > runmax - 1.02} to per-row u16 lists with a deterministic
// quad-prefix-scan (phase wn=0 then wn=1).
// Superset proof: support z > tau >= zmax-1 >= runmax-1 > runmax-1.02.
// ---------------------------------------------------------------------------
__device__ __forceinline__ unsigned f2tf32(float f) {
    unsigned u;
    asm("cvt.rna.tf32.f32 %0, %1;" : "=r"(u) : "f"(f));
    return u;
}

#define QK_LDS 68
#define SCR_SMEM (2 * 128 * QK_LDS * 4 + 128 * CAPS * 2 + 128 * 4 + 128 * 4)

__global__ __launch_bounds__(256) void qk_screen(
    const float* __restrict__ Q, const float* __restrict__ K,
    unsigned short* __restrict__ cand, int* __restrict__ ccnt,
    float* __restrict__ rmaxf)
{
    extern __shared__ unsigned sm[];
    unsigned* Qs = sm;                                   // [128][68]
    unsigned* Ks = sm + 128 * QK_LDS;                    // [128][68]
    unsigned short* jl = (unsigned short*)(sm + 2 * 128 * QK_LDS); // [128][CAPS]
    unsigned* rmaxs = (unsigned*)(jl + 128 * CAPS);      // [128] encoded
    int* cnts = (int*)(rmaxs + 128);                     // [128]

    int tid = threadIdx.x;
    int wid = tid >> 5, lane = tid & 31;
    int wm = wid & 3;        // 32-row slab
    int wn = wid >> 2;       // 64-col slab
    int g = lane >> 2;
    int tg = lane & 3;
    int qb = lane & ~3;      // quad base lane

    int bh = blockIdx.z;
    int q0 = blockIdx.x * 128;

    for (int r = tid; r < 128; r += 256) { rmaxs[r] = 0u; cnts[r] = 0; }

    // stage Q tile once
    const float* Qg = Q + ((long)bh * Ss + q0) * DHh;
#pragma unroll
    for (int p = 0; p < 8; ++p) {
        int r = (tid >> 4) + p * 16;
        int c = (tid & 15) * 4;
        float4 v = *(const float4*)(Qg + r * DHh + c);
        unsigned* q = Qs + r * QK_LDS + c;
        q[0] = f2tf32(v.x); q[1] = f2tf32(v.y);
        q[2] = f2tf32(v.z); q[3] = f2tf32(v.w);
    }
    __syncthreads();

    for (int t = 0; t < 16; ++t) {
        // stage K tile
        const float* Kg = K + ((long)bh * Ss + t * 128) * DHh;
#pragma unroll
        for (int p = 0; p < 8; ++p) {
            int r = (tid >> 4) + p * 16;
            int c = (tid & 15) * 4;
            float4 v = *(const float4*)(Kg + r * DHh + c);
            unsigned* kk = Ks + r * QK_LDS + c;
            kk[0] = f2tf32(v.x); kk[1] = f2tf32(v.y);
            kk[2] = f2tf32(v.z); kk[3] = f2tf32(v.w);
        }
        __syncthreads();

        // mma for this 128x128 tile
        float acc[2][8][4];
#pragma unroll
        for (int mt = 0; mt < 2; ++mt)
#pragma unroll
            for (int nt = 0; nt < 8; ++nt)
#pragma unroll
                for (int e = 0; e < 4; ++e) acc[mt][nt][e] = 0.0f;

#pragma unroll
        for (int ks = 0; ks < 8; ++ks) {
            int kc = ks * 8;
            unsigned a[2][4];
#pragma unroll
            for (int mt = 0; mt < 2; ++mt) {
                int r = wm * 32 + mt * 16 + g;
                a[mt][0] = Qs[(r) * QK_LDS + kc + tg];
                a[mt][1] = Qs[(r + 8) * QK_LDS + kc + tg];
                a[mt][2] = Qs[(r) * QK_LDS + kc + tg + 4];
                a[mt][3] = Qs[(r + 8) * QK_LDS + kc + tg + 4];
            }
            unsigned b[8][2];
#pragma unroll
            for (int nt = 0; nt < 8; ++nt) {
                int n = wn * 64 + nt * 8 + g;
                b[nt][0] = Ks[n * QK_LDS + kc + tg];
                b[nt][1] = Ks[n * QK_LDS + kc + tg + 4];
            }
#pragma unroll
            for (int mt = 0; mt < 2; ++mt)
#pragma unroll
                for (int nt = 0; nt < 8; ++nt) {
                    asm volatile(
                        "mma.sync.aligned.m16n8k8.row.col.f32.tf32.tf32.f32 "
                        "{%0,%1,%2,%3}, {%4,%5,%6,%7}, {%8,%9}, {%0,%1,%2,%3};"
                        : "+f"(acc[mt][nt][0]), "+f"(acc[mt][nt][1]),
                          "+f"(acc[mt][nt][2]), "+f"(acc[mt][nt][3])
                        : "r"(a[mt][0]), "r"(a[mt][1]), "r"(a[mt][2]), "r"(a[mt][3]),
                          "r"(b[nt][0]), "r"(b[nt][1]));
                }
        }

        // running row max (order-independent atomicMax -> deterministic)
#pragma unroll
        for (int mt = 0; mt < 2; ++mt) {
            float m0 = -3e38f, m1 = -3e38f;
#pragma unroll
            for (int nt = 0; nt < 8; ++nt) {
                m0 = fmaxf(m0, fmaxf(acc[mt][nt][0], acc[mt][nt][1]));
                m1 = fmaxf(m1, fmaxf(acc[mt][nt][2], acc[mt][nt][3]));
            }
#pragma unroll
            for (int off = 1; off <= 2; off <<= 1) {
                m0 = fmaxf(m0, __shfl_xor_sync(0xffffffffu, m0, off));
                m1 = fmaxf(m1, __shfl_xor_sync(0xffffffffu, m1, off));
            }
            if (tg == 0) {
                atomicMax(&rmaxs[wm * 32 + mt * 16 + g], enc_f(m0));
                atomicMax(&rmaxs[wm * 32 + mt * 16 + g + 8], enc_f(m1));
            }
        }
        __syncthreads();

        // deterministic screening: wn=0 appends first, then wn=1
        for (int phase = 0; phase < 2; ++phase) {
            if (wn == phase) {
#pragma unroll
                for (int mt = 0; mt < 2; ++mt) {
#pragma unroll
                    for (int half = 0; half < 2; ++half) {
                        int r = wm * 32 + mt * 16 + g + half * 8;
                        float thr = dec_f(rmaxs[r]) - 1.02f;
                        unsigned m = 0;
#pragma unroll
                        for (int nt = 0; nt < 8; ++nt) {
#pragma unroll
                            for (int ee = 0; ee < 2; ++ee)
                                if (acc[mt][nt][half * 2 + ee] > thr)
                                    m |= 1u << (nt * 2 + ee);
                        }
                        int c = __popc(m);
                        int c0 = __shfl_sync(0xffffffffu, c, qb);
                        int c1 = __shfl_sync(0xffffffffu, c, qb + 1);
                        int c2 = __shfl_sync(0xffffffffu, c, qb + 2);
                        int c3 = __shfl_sync(0xffffffffu, c, qb + 3);
                        int pre = (tg > 0 ? c0 : 0) + (tg > 1 ? c1 : 0) + (tg > 2 ? c2 : 0);
                        int tot = c0 + c1 + c2 + c3;
                        int base = cnts[r];        // stable: quad-only writer, post-sync
                        int pos = base + pre;
                        while (m) {
                            int bit = __ffs(m) - 1; m &= m - 1;
                            int j = t * 128 + wn * 64 + (bit >> 1) * 8 + tg * 2 + (bit & 1);
                            if (pos < CAPS) jl[r * CAPS + pos] = (unsigned short)j;
                            ++pos;
                        }
                        __syncwarp();              // all quad reads of base done
                        if (tg == 0) cnts[r] = base + tot;
                        __syncwarp();
                    }
                }
            }
            __syncthreads();
        }
    }

    // write results
    long rowg0 = (long)bh * Ss + q0;
    for (int r = tid; r < 128; r += 256) {
        ccnt[rowg0 + r] = cnts[r];
        rmaxf[rowg0 + r] = dec_f(rmaxs[r]);
    }
    __syncthreads();
    for (int r = wid; r < 128; r += 8) {
        int c = min(cnts[r], CAPS);
        unsigned short* dst = cand + (rowg0 + r) * CAPS;
        for (int e = lane; e < c; e += 32) dst[e] = jl[r * CAPS + e];
    }
}

// ---------------------------------------------------------------------------
// Finish: exact fp32 recompute of candidates, Michelot tau, heads, avg.
// Warp w = head w of row (b,i). K (8MB) and V (1MB) are L2-resident.
// ---------------------------------------------------------------------------
__global__ __launch_bounds__(256) void sparse_final(
    const unsigned short* __restrict__ cand, const int* __restrict__ ccnt,
    const float* __restrict__ rmaxf,
    const float* __restrict__ Q, const float* __restrict__ K,
    const float* __restrict__ V,
    float* __restrict__ heads, float* __restrict__ avg_out)
{
    __shared__ float s_z[Hh][CAPS];
    __shared__ short s_j[Hh][CAPS];
    __shared__ float s_tau[Hh];
    __shared__ int   s_cnt[Hh];
    __shared__ float s_qv[Hh][DHh];
    __shared__ float s_avg[Ss];

    int row = blockIdx.x;
    int b = row >> 11;
    int i = row & 2047;
    int tid = threadIdx.x;
    int w = tid >> 5;
    int lane = tid & 31;

    for (int j = tid; j < Ss; j += 256) s_avg[j] = 0.0f;

    long bhrow = ((long)b * Hh + w) * Ss + i;
    const float* Qrow = Q + bhrow * DHh;
    const float* Kbh  = K + (((long)b * Hh + w) * Ss) * (long)DHh;
    const float* Vb   = V + (long)b * Ss * DHh;
    float q0 = Qrow[lane], q1 = Qrow[lane + 32];

    int n = ccnt[bhrow];
    float o0 = 0.0f, o1 = 0.0f;

    if (n <= CAPS) {
        // load candidate indices
        const unsigned short* cr = cand + bhrow * CAPS;
        for (int e = lane; e < n; e += 32) s_j[w][e] = (short)cr[e];
        __syncwarp();

        // exact fp32 recompute (2-way unrolled for MLP)
        int e = 0;
        for (; e + 2 <= n; e += 2) {
            int j0 = s_j[w][e], j1 = s_j[w][e + 1];
            const float* K0 = Kbh + (long)j0 * DHh;
            const float* K1 = Kbh + (long)j1 * DHh;
            float p0 = q0 * K0[lane] + q1 * K0[lane + 32];
            float p1 = q0 * K1[lane] + q1 * K1[lane + 32];
#pragma unroll
            for (int off = 16; off; off >>= 1) {
                p0 += __shfl_xor_sync(0xffffffffu, p0, off);
                p1 += __shfl_xor_sync(0xffffffffu, p1, off);
            }
            if (lane == 0) { s_z[w][e] = p0; s_z[w][e + 1] = p1; }
        }
        if (e < n) {
            int j0 = s_j[w][e];
            const float* K0 = Kbh + (long)j0 * DHh;
            float p0 = q0 * K0[lane] + q1 * K0[lane + 32];
#pragma unroll
            for (int off = 16; off; off >>= 1)
                p0 += __shfl_xor_sync(0xffffffffu, p0, off);
            if (lane == 0) s_z[w][e] = p0;
        }
        __syncwarp();

        // exact tau: Michelot over candidate superset
        float tau = rmaxf[bhrow] - 1.02f;
        for (int it = 0; it < 48; ++it) {
            float s = 0.0f; int c = 0;
            for (int e2 = lane; e2 < n; e2 += 32) {
                float zz = s_z[w][e2];
                if (zz > tau) { s += zz; c++; }
            }
#pragma unroll
            for (int off = 16; off; off >>= 1) {
                s += __shfl_xor_sync(0xffffffffu, s, off);
                c += __shfl_xor_sync(0xffffffffu, c, off);
            }
            float nt2 = (s - 1.0f) / (float)c;
            if (nt2 == tau) break;
            tau = nt2;
        }
        if (lane == 0) { s_tau[w] = tau; s_cnt[w] = n; }

        // heads from sparse support
        for (int e2 = 0; e2 < n; ++e2) {
            float p = s_z[w][e2] - tau;
            if (p > 0.0f) {
                const float* Vr = Vb + (long)s_j[w][e2] * DHh;
                o0 += p * Vr[lane];
                o1 += p * Vr[lane + 32];
            }
        }
    } else {
        // -------- overflow fallback (unreachable for this input) --------
        s_qv[w][lane] = q0; s_qv[w][lane + 32] = q1;
        __syncwarp();
        float tau = rmaxf[bhrow] - 1.02f;
        for (int it = 0; it < 48; ++it) {
            float s = 0.0f; int c = 0;
            for (int j = lane; j < Ss; j += 32) {
                const float* Kr = Kbh + (long)j * DHh;
                float zz = 0.0f;
#pragma unroll
                for (int d = 0; d < DHh; ++d) zz += s_qv[w][d] * Kr[d];
                if (zz > tau) { s += zz; c++; }
            }
#pragma unroll
            for (int off = 16; off; off >>= 1) {
                s += __shfl_xor_sync(0xffffffffu, s, off);
                c += __shfl_xor_sync(0xffffffffu, c, off);
            }
            float nt2 = (s - 1.0f) / (float)c;
            if (nt2 == tau) break;
            tau = nt2;
        }
        // dense heads + avg (warp-cooperative per key)
        for (int j = 0; j < Ss; ++j) {
            const float* Kr = Kbh + (long)j * DHh;
            float p = q0 * Kr[lane] + q1 * Kr[lane + 32];
#pragma unroll
            for (int off = 16; off; off >>= 1)
                p += __shfl_xor_sync(0xffffffffu, p, off);
            p -= tau;
            if (p > 0.0f) {
                o0 += p * Vb[(long)j * DHh + lane];
                o1 += p * Vb[(long)j * DHh + lane + 32];
                if (lane == 0) atomicAdd(&s_avg[j], p);
            }
        }
        if (lane == 0) { s_tau[w] = tau; s_cnt[w] = 0; }
    }

    long hbase = (long)row * Dd + w * DHh;
    heads[hbase + lane] = o0;
    heads[hbase + lane + 32] = o1;

    __syncthreads();

    // avg_attention: deterministic ownership scan over candidate lists
    float rv[8];
#pragma unroll
    for (int k = 0; k < 8; ++k) rv[k] = s_avg[tid + k * 256];
#pragma unroll
    for (int h = 0; h < Hh; ++h) {
        int c = s_cnt[h];
        float th = s_tau[h];
        for (int e = 0; e < c; ++e) {
            int j = s_j[h][e];
            if ((j & 255) == tid) {
                float p = s_z[h][e] - th;
                if (p > 0.0f) rv[j >> 8] += p;
            }
        }
    }
    long abase = ((long)b * Ss + i) * (long)Ss;
#pragma unroll
    for (int k = 0; k < 8; ++k)
        avg_out[abase + tid + k * 256] = 0.125f * rv[k];
}

// ---------------------------------------------------------------------------
extern "C" void kernel_launch(void* const* d_in, const int* in_sizes, int n_in,
                              void* d_out, int out_size)
{
    const float* x    = (const float*)d_in[0];
    const float* Wq   = (const float*)d_in[1];
    const float* bq   = (const float*)d_in[2];
    const float* Wk   = (const float*)d_in[3];
    const float* bk   = (const float*)d_in[4];
    const float* Wv   = (const float*)d_in[5];
    const float* bv   = (const float*)d_in[6];
    const float* Wout = (const float*)d_in[7];
    const float* bout = (const float*)d_in[8];

    float* out   = (float*)d_out;
    float* x_out = out;                              // [B,S,D]
    float* avg   = out + (long)Bb * Ss * Dd;         // [B,S,S]

    float *Qp, *Kp, *Vp, *Hp, *Rp;
    unsigned short* Cp;
    int* Np;
    cudaGetSymbolAddress((void**)&Qp, g_Q);
    cudaGetSymbolAddress((void**)&Kp, g_K);
    cudaGetSymbolAddress((void**)&Vp, g_V);
    cudaGetSymbolAddress((void**)&Hp, g_heads);
    cudaGetSymbolAddress((void**)&Cp, g_cand);
    cudaGetSymbolAddress((void**)&Np, g_ccnt);
    cudaGetSymbolAddress((void**)&Rp, g_rmax);

    cudaFuncSetAttribute(qk_screen,
                         cudaFuncAttributeMaxDynamicSharedMemorySize,
                         SCR_SMEM);

    const int M = Bb * Ss;   // 4096

    // Q = x@Wq + bq  -> [B,H,S,dh]
    sgemm_128x64<<<dim3(M / 128, Dd / 64, 1), 256>>>(
        x, Dd, 0, Wq, Dd, 0, 0, bq, Qp, 0, 0, 1, Dd);
    // K = x@Wk + bk  -> [B,H,S,dh]
    sgemm_128x64<<<dim3(M / 128, Dd / 64, 1), 256>>>(
        x, Dd, 0, Wk, Dd, 0, 0, bk, Kp, 0, 0, 1, Dd);
    // V = x@Wv + bv  -> [B,S,dh]
    sgemm_128x64<<<dim3(M / 128, DHh / 64, 1), 256>>>(
        x, Dd, 0, Wv, DHh, 0, 0, bv, Vp, DHh, 0, 0, Dd);

    // fused QK + candidate screening (no logits materialization)
    qk_screen<<<dim3(Ss / 128, 1, Bb * Hh), 256, SCR_SMEM>>>(
        Qp, Kp, Cp, Np, Rp);

    // exact sparsemax + heads + avg from candidate lists
    sparse_final<<<Bb * Ss, 256>>>(Cp, Np, Rp, Qp, Kp, Vp, Hp, avg);

    // x_out = heads @ Wout + bout
    sgemm_128x64<<<dim3(M / 128, Dd / 64, 1), 256>>>(
        Hp, Dd, 0, Wout, Dd, 0, 0, bout, x_out, Dd, 0, 0, Dd);
}

// round 7
// speedup vs baseline: 4.2593x; 4.2593x over previous
#include <cuda_runtime.h>

#define Bb 2
#define Ss 2048
#define Dd 512
#define Hh 8
#define DHh 64
#define CAPS 160     // candidate cap per row (expected ~60-100 w/ running-max screen)

// Scratch (device globals: no runtime allocation allowed)
__device__ float          g_Q[Bb * Hh * Ss * DHh];       // [B,H,S,dh]  8 MB
__device__ float          g_K[Bb * Hh * Ss * DHh];       // [B,H,S,dh]  8 MB
__device__ float          g_V[Bb * Ss * DHh];            // [B,S,dh]    1 MB
__device__ float          g_heads[Bb * Ss * Dd];         // [B,S,D]     8 MB
__device__ unsigned short g_cand[Bb * Hh * Ss * CAPS];   // cand indices
__device__ int            g_ccnt[Bb * Hh * Ss];          // cand counts
__device__ float          g_rmax[Bb * Hh * Ss];          // tf32 row maxes

// monotone float<->unsigned encoding for atomicMax on floats
__device__ __forceinline__ unsigned enc_f(float f) {
    unsigned b = __float_as_uint(f);
    return (f >= 0.0f) ? (b | 0x80000000u) : ~b;
}
__device__ __forceinline__ float dec_f(unsigned u) {
    return (u & 0x80000000u) ? __uint_as_float(u & 0x7fffffffu)
                             : __uint_as_float(~u);
}

// ---------------------------------------------------------------------------
// fp32 SGEMM (projections / output): C = A (MxK) * B (KxN or NxK) + bias
// ---------------------------------------------------------------------------
__global__ __launch_bounds__(256) void sgemm_128x64(
    const float* __restrict__ A, int lda, long sA,
    const float* __restrict__ Bmat, int ldb, long sB, int transB,
    const float* __restrict__ bias,
    float* __restrict__ C, int ldc, long sC, int headMajorC,
    int Kdim)
{
    const int BM = 128, BN = 64, BK = 16;
    __shared__ float As[BK][BM + 4];
    __shared__ float Bs[BK][BN + 4];

    const float* Ab = A + (long)blockIdx.z * sA;
    const float* Bp = Bmat + (long)blockIdx.z * sB;
    float* Cb = C + (long)blockIdx.z * sC;

    int tid = threadIdx.x;
    int tx = tid & 15;
    int ty = tid >> 4;
    int m0 = blockIdx.x * BM;
    int n0 = blockIdx.y * BN;

    int ar = tid >> 1;
    int ac = (tid & 1) * 8;
    int br_n = tid >> 2;
    int bc_k = (tid & 3) * 4;
    int br_k = tid >> 4;
    int bc_n = (tid & 15) * 4;

    float acc[8][4];
#pragma unroll
    for (int i = 0; i < 8; ++i)
#pragma unroll
        for (int j = 0; j < 4; ++j) acc[i][j] = 0.0f;

    for (int k0 = 0; k0 < Kdim; k0 += BK) {
        {
            const float* ap = Ab + (long)(m0 + ar) * lda + k0 + ac;
            float4 v0 = *(const float4*)(ap);
            float4 v1 = *(const float4*)(ap + 4);
            As[ac + 0][ar] = v0.x; As[ac + 1][ar] = v0.y;
            As[ac + 2][ar] = v0.z; As[ac + 3][ar] = v0.w;
            As[ac + 4][ar] = v1.x; As[ac + 5][ar] = v1.y;
            As[ac + 6][ar] = v1.z; As[ac + 7][ar] = v1.w;
        }
        if (transB) {
            float4 v = *(const float4*)(Bp + (long)(n0 + br_n) * ldb + k0 + bc_k);
            Bs[bc_k + 0][br_n] = v.x; Bs[bc_k + 1][br_n] = v.y;
            Bs[bc_k + 2][br_n] = v.z; Bs[bc_k + 3][br_n] = v.w;
        } else {
            float4 v = *(const float4*)(Bp + (long)(k0 + br_k) * ldb + n0 + bc_n);
            *(float4*)&Bs[br_k][bc_n] = v;
        }
        __syncthreads();

#pragma unroll
        for (int k = 0; k < BK; ++k) {
            float a[8], b[4];
            *(float4*)&a[0] = *(const float4*)&As[k][ty * 8];
            *(float4*)&a[4] = *(const float4*)&As[k][ty * 8 + 4];
            *(float4*)&b[0] = *(const float4*)&Bs[k][tx * 4];
#pragma unroll
            for (int i = 0; i < 8; ++i)
#pragma unroll
                for (int j = 0; j < 4; ++j)
                    acc[i][j] += a[i] * b[j];
        }
        __syncthreads();
    }

    float4 bv = make_float4(0.f, 0.f, 0.f, 0.f);
    if (bias) bv = *(const float4*)(bias + n0 + tx * 4);

#pragma unroll
    for (int i = 0; i < 8; ++i) {
        int m = m0 + ty * 8 + i;
        float4 o;
        o.x = acc[i][0] + bv.x;
        o.y = acc[i][1] + bv.y;
        o.z = acc[i][2] + bv.z;
        o.w = acc[i][3] + bv.w;
        long addr;
        if (headMajorC) {
            int bb = m >> 11;
            int ss = m & 2047;
            int hh = n0 >> 6;
            addr = ((((long)bb * Hh + hh) * Ss) + ss) * DHh + tx * 4;
        } else {
            addr = (long)m * ldc + n0 + tx * 4;
        }
        *(float4*)(Cb + addr) = o;
    }
}

// ---------------------------------------------------------------------------
// Fused QK + screening: never materializes logits.
// CTA = (q-tile of 128, bh). Streams 16 K-tiles via tf32 mma; keeps a running
// per-row max (encoded shared atomicMax, deterministic) and appends candidate
// key indices {z > runmax - 1.02} to per-row u16 lists.
// Superset proof: support z > tau >= zmax-1 >= runmax-1 > runmax-1.02.
// ---------------------------------------------------------------------------
__device__ __forceinline__ unsigned f2tf32(float f) {
    unsigned u;
    asm("cvt.rna.tf32.f32 %0, %1;" : "=r"(u) : "f"(f));
    return u;
}

#define QK_LDS 68
#define SCR_SMEM (2 * 128 * QK_LDS * 4 + 128 * CAPS * 2 + 128 * 4 + 128 * 4)

__global__ __launch_bounds__(256) void qk_screen(
    const float* __restrict__ Q, const float* __restrict__ K,
    unsigned short* __restrict__ cand, int* __restrict__ ccnt,
    float* __restrict__ rmaxf)
{
    extern __shared__ unsigned sm[];
    unsigned* Qs = sm;                                   // [128][68]
    unsigned* Ks = sm + 128 * QK_LDS;                    // [128][68]
    unsigned short* jl = (unsigned short*)(sm + 2 * 128 * QK_LDS); // [128][CAPS]
    unsigned* rmaxs = (unsigned*)(jl + 128 * CAPS);      // [128] encoded
    int* cnts = (int*)(rmaxs + 128);                     // [128]

    int tid = threadIdx.x;
    int wid = tid >> 5, lane = tid & 31;
    int wm = wid & 3;        // 32-row slab
    int wn = wid >> 2;       // 64-col slab
    int g = lane >> 2;
    int tg = lane & 3;
    int qb = lane & ~3;      // quad base lane

    int bh = blockIdx.z;
    int q0 = blockIdx.x * 128;

    for (int r = tid; r < 128; r += 256) { rmaxs[r] = 0u; cnts[r] = 0; }

    // stage Q tile once
    const float* Qg = Q + ((long)bh * Ss + q0) * DHh;
#pragma unroll
    for (int p = 0; p < 8; ++p) {
        int r = (tid >> 4) + p * 16;
        int c = (tid & 15) * 4;
        float4 v = *(const float4*)(Qg + r * DHh + c);
        unsigned* q = Qs + r * QK_LDS + c;
        q[0] = f2tf32(v.x); q[1] = f2tf32(v.y);
        q[2] = f2tf32(v.z); q[3] = f2tf32(v.w);
    }
    __syncthreads();

    for (int t = 0; t < 16; ++t) {
        // stage K tile
        const float* Kg = K + ((long)bh * Ss + t * 128) * DHh;
#pragma unroll
        for (int p = 0; p < 8; ++p) {
            int r = (tid >> 4) + p * 16;
            int c = (tid & 15) * 4;
            float4 v = *(const float4*)(Kg + r * DHh + c);
            unsigned* kk = Ks + r * QK_LDS + c;
            kk[0] = f2tf32(v.x); kk[1] = f2tf32(v.y);
            kk[2] = f2tf32(v.z); kk[3] = f2tf32(v.w);
        }
        __syncthreads();

        // mma for this 128x128 tile
        float acc[2][8][4];
#pragma unroll
        for (int mt = 0; mt < 2; ++mt)
#pragma unroll
            for (int nt = 0; nt < 8; ++nt)
#pragma unroll
                for (int e = 0; e < 4; ++e) acc[mt][nt][e] = 0.0f;

#pragma unroll
        for (int ks = 0; ks < 8; ++ks) {
            int kc = ks * 8;
            unsigned a[2][4];
#pragma unroll
            for (int mt = 0; mt < 2; ++mt) {
                int r = wm * 32 + mt * 16 + g;
                a[mt][0] = Qs[(r) * QK_LDS + kc + tg];
                a[mt][1] = Qs[(r + 8) * QK_LDS + kc + tg];
                a[mt][2] = Qs[(r) * QK_LDS + kc + tg + 4];
                a[mt][3] = Qs[(r + 8) * QK_LDS + kc + tg + 4];
            }
            unsigned b[8][2];
#pragma unroll
            for (int nt = 0; nt < 8; ++nt) {
                int n = wn * 64 + nt * 8 + g;
                b[nt][0] = Ks[n * QK_LDS + kc + tg];
                b[nt][1] = Ks[n * QK_LDS + kc + tg + 4];
            }
#pragma unroll
            for (int mt = 0; mt < 2; ++mt)
#pragma unroll
                for (int nt = 0; nt < 8; ++nt) {
                    asm volatile(
                        "mma.sync.aligned.m16n8k8.row.col.f32.tf32.tf32.f32 "
                        "{%0,%1,%2,%3}, {%4,%5,%6,%7}, {%8,%9}, {%0,%1,%2,%3};"
                        : "+f"(acc[mt][nt][0]), "+f"(acc[mt][nt][1]),
                          "+f"(acc[mt][nt][2]), "+f"(acc[mt][nt][3])
                        : "r"(a[mt][0]), "r"(a[mt][1]), "r"(a[mt][2]), "r"(a[mt][3]),
                          "r"(b[nt][0]), "r"(b[nt][1]));
                }
        }

        // running row max (order-independent atomicMax -> deterministic)
#pragma unroll
        for (int mt = 0; mt < 2; ++mt) {
            float m0 = -3e38f, m1 = -3e38f;
#pragma unroll
            for (int nt = 0; nt < 8; ++nt) {
                m0 = fmaxf(m0, fmaxf(acc[mt][nt][0], acc[mt][nt][1]));
                m1 = fmaxf(m1, fmaxf(acc[mt][nt][2], acc[mt][nt][3]));
            }
#pragma unroll
            for (int off = 1; off <= 2; off <<= 1) {
                m0 = fmaxf(m0, __shfl_xor_sync(0xffffffffu, m0, off));
                m1 = fmaxf(m1, __shfl_xor_sync(0xffffffffu, m1, off));
            }
            if (tg == 0) {
                atomicMax(&rmaxs[wm * 32 + mt * 16 + g], enc_f(m0));
                atomicMax(&rmaxs[wm * 32 + mt * 16 + g + 8], enc_f(m1));
            }
        }
        __syncthreads();

        // deterministic screening: wn=0 appends first, then wn=1
        for (int phase = 0; phase < 2; ++phase) {
            if (wn == phase) {
#pragma unroll
                for (int mt = 0; mt < 2; ++mt) {
#pragma unroll
                    for (int half = 0; half < 2; ++half) {
                        int r = wm * 32 + mt * 16 + g + half * 8;
                        float thr = dec_f(rmaxs[r]) - 1.02f;
                        unsigned m = 0;
#pragma unroll
                        for (int nt = 0; nt < 8; ++nt) {
#pragma unroll
                            for (int ee = 0; ee < 2; ++ee)
                                if (acc[mt][nt][half * 2 + ee] > thr)
                                    m |= 1u << (nt * 2 + ee);
                        }
                        int c = __popc(m);
                        int c0 = __shfl_sync(0xffffffffu, c, qb);
                        int c1 = __shfl_sync(0xffffffffu, c, qb + 1);
                        int c2 = __shfl_sync(0xffffffffu, c, qb + 2);
                        int c3 = __shfl_sync(0xffffffffu, c, qb + 3);
                        int pre = (tg > 0 ? c0 : 0) + (tg > 1 ? c1 : 0) + (tg > 2 ? c2 : 0);
                        int tot = c0 + c1 + c2 + c3;
                        int base = cnts[r];        // stable: quad-only writer, post-sync
                        int pos = base + pre;
                        while (m) {
                            int bit = __ffs(m) - 1; m &= m - 1;
                            int j = t * 128 + wn * 64 + (bit >> 1) * 8 + tg * 2 + (bit & 1);
                            if (pos < CAPS) jl[r * CAPS + pos] = (unsigned short)j;
                            ++pos;
                        }
                        __syncwarp();              // all quad reads of base done
                        if (tg == 0) cnts[r] = base + tot;
                        __syncwarp();
                    }
                }
            }
            __syncthreads();
        }
    }

    // write results
    long rowg0 = (long)bh * Ss + q0;
    for (int r = tid; r < 128; r += 256) {
        ccnt[rowg0 + r] = cnts[r];
        rmaxf[rowg0 + r] = dec_f(rmaxs[r]);
    }
    __syncthreads();
    for (int r = wid; r < 128; r += 8) {
        int c = min(cnts[r], CAPS);
        unsigned short* dst = cand + (rowg0 + r) * CAPS;
        for (int e = lane; e < c; e += 32) dst[e] = jl[r * CAPS + e];
    }
}

// ---------------------------------------------------------------------------
// Finish: exact fp32 candidate logits, Michelot tau, heads, avg.
// Warp w = head w of row (b,i). Overflow (rare) takes a CHEAP coalesced dense
// re-screen against the FINAL rowmax (count ~30), then joins the common path.
// ---------------------------------------------------------------------------
__global__ __launch_bounds__(256) void sparse_final(
    const unsigned short* __restrict__ cand, const int* __restrict__ ccnt,
    const float* __restrict__ rmaxf,
    const float* __restrict__ Q, const float* __restrict__ K,
    const float* __restrict__ V,
    float* __restrict__ heads, float* __restrict__ avg_out)
{
    __shared__ float s_z[Hh][CAPS];
    __shared__ short s_j[Hh][CAPS];
    __shared__ float s_tau[Hh];
    __shared__ int   s_cnt[Hh];

    int row = blockIdx.x;
    int b = row >> 11;
    int i = row & 2047;
    int tid = threadIdx.x;
    int w = tid >> 5;
    int lane = tid & 31;

    long bhrow = ((long)b * Hh + w) * Ss + i;
    const float* Qrow = Q + bhrow * DHh;
    const float* Kbh  = K + (((long)b * Hh + w) * Ss) * (long)DHh;
    const float* Vb   = V + (long)b * Ss * DHh;
    float q0 = Qrow[lane], q1 = Qrow[lane + 32];

    int n = ccnt[bhrow];

    if (n <= CAPS) {
        // load candidate indices, recompute exact fp32 logits (2-way ILP)
        const unsigned short* cr = cand + bhrow * CAPS;
        for (int e = lane; e < n; e += 32) s_j[w][e] = (short)cr[e];
        __syncwarp();

        int e = 0;
        for (; e + 2 <= n; e += 2) {
            int j0 = s_j[w][e], j1 = s_j[w][e + 1];
            const float* K0 = Kbh + (long)j0 * DHh;
            const float* K1 = Kbh + (long)j1 * DHh;
            float p0 = q0 * K0[lane] + q1 * K0[lane + 32];
            float p1 = q0 * K1[lane] + q1 * K1[lane + 32];
#pragma unroll
            for (int off = 16; off; off >>= 1) {
                p0 += __shfl_xor_sync(0xffffffffu, p0, off);
                p1 += __shfl_xor_sync(0xffffffffu, p1, off);
            }
            if (lane == 0) { s_z[w][e] = p0; s_z[w][e + 1] = p1; }
        }
        if (e < n) {
            int j0 = s_j[w][e];
            const float* K0 = Kbh + (long)j0 * DHh;
            float p0 = q0 * K0[lane] + q1 * K0[lane + 32];
#pragma unroll
            for (int off = 16; off; off >>= 1)
                p0 += __shfl_xor_sync(0xffffffffu, p0, off);
            if (lane == 0) s_z[w][e] = p0;
        }
        __syncwarp();
    } else {
        // RARE: coalesced dense re-screen vs FINAL rowmax-1.02 (exact fp32,
        // 4 keys in flight; resulting count ~30 << CAPS). Deterministic:
        // ascending j, exact values, deterministic rmaxf.
        float thrF = rmaxf[bhrow] - 1.02f;
        int cnt2 = 0;
        for (int j0 = 0; j0 < Ss; j0 += 4) {
            float p[4];
#pragma unroll
            for (int u = 0; u < 4; ++u) {
                const float* Kr = Kbh + (long)(j0 + u) * DHh;
                p[u] = q0 * Kr[lane] + q1 * Kr[lane + 32];
            }
#pragma unroll
            for (int off = 16; off; off >>= 1)
#pragma unroll
                for (int u = 0; u < 4; ++u)
                    p[u] += __shfl_xor_sync(0xffffffffu, p[u], off);
            if (lane == 0) {
#pragma unroll
                for (int u = 0; u < 4; ++u) {
                    if (p[u] > thrF && cnt2 < CAPS) {
                        s_z[w][cnt2] = p[u];
                        s_j[w][cnt2] = (short)(j0 + u);
                        ++cnt2;
                    }
                }
            }
        }
        n = __shfl_sync(0xffffffffu, cnt2, 0);
        __syncwarp();
    }

    // exact tau: Michelot fixed-point over candidate superset
    float tau = rmaxf[bhrow] - 1.02f;
    for (int it = 0; it < 48; ++it) {
        float s = 0.0f; int c = 0;
        for (int e2 = lane; e2 < n; e2 += 32) {
            float zz = s_z[w][e2];
            if (zz > tau) { s += zz; c++; }
        }
#pragma unroll
        for (int off = 16; off; off >>= 1) {
            s += __shfl_xor_sync(0xffffffffu, s, off);
            c += __shfl_xor_sync(0xffffffffu, c, off);
        }
        float nt2 = (s - 1.0f) / (float)c;
        if (nt2 == tau) break;
        tau = nt2;
    }
    if (lane == 0) { s_tau[w] = tau; s_cnt[w] = n; }

    // heads from sparse support
    float o0 = 0.0f, o1 = 0.0f;
    for (int e2 = 0; e2 < n; ++e2) {
        float p = s_z[w][e2] - tau;
        if (p > 0.0f) {
            const float* Vr = Vb + (long)s_j[w][e2] * DHh;
            o0 += p * Vr[lane];
            o1 += p * Vr[lane + 32];
        }
    }
    long hbase = (long)row * Dd + w * DHh;
    heads[hbase + lane] = o0;
    heads[hbase + lane + 32] = o1;

    __syncthreads();

    // avg_attention: deterministic ownership scan over candidate lists
    float rv[8];
#pragma unroll
    for (int k = 0; k < 8; ++k) rv[k] = 0.0f;
#pragma unroll
    for (int h = 0; h < Hh; ++h) {
        int c = s_cnt[h];
        float th = s_tau[h];
        for (int e = 0; e < c; ++e) {
            int j = s_j[h][e];
            if ((j & 255) == tid) {
                float p = s_z[h][e] - th;
                if (p > 0.0f) rv[j >> 8] += p;
            }
        }
    }
    long abase = ((long)b * Ss + i) * (long)Ss;
#pragma unroll
    for (int k = 0; k < 8; ++k)
        avg_out[abase + tid + k * 256] = 0.125f * rv[k];
}

// ---------------------------------------------------------------------------
extern "C" void kernel_launch(void* const* d_in, const int* in_sizes, int n_in,
                              void* d_out, int out_size)
{
    const float* x    = (const float*)d_in[0];
    const float* Wq   = (const float*)d_in[1];
    const float* bq   = (const float*)d_in[2];
    const float* Wk   = (const float*)d_in[3];
    const float* bk   = (const float*)d_in[4];
    const float* Wv   = (const float*)d_in[5];
    const float* bv   = (const float*)d_in[6];
    const float* Wout = (const float*)d_in[7];
    const float* bout = (const float*)d_in[8];

    float* out   = (float*)d_out;
    float* x_out = out;                              // [B,S,D]
    float* avg   = out + (long)Bb * Ss * Dd;         // [B,S,S]

    float *Qp, *Kp, *Vp, *Hp, *Rp;
    unsigned short* Cp;
    int* Np;
    cudaGetSymbolAddress((void**)&Qp, g_Q);
    cudaGetSymbolAddress((void**)&Kp, g_K);
    cudaGetSymbolAddress((void**)&Vp, g_V);
    cudaGetSymbolAddress((void**)&Hp, g_heads);
    cudaGetSymbolAddress((void**)&Cp, g_cand);
    cudaGetSymbolAddress((void**)&Np, g_ccnt);
    cudaGetSymbolAddress((void**)&Rp, g_rmax);

    cudaFuncSetAttribute(qk_screen,
                         cudaFuncAttributeMaxDynamicSharedMemorySize,
                         SCR_SMEM);

    const int M = Bb * Ss;   // 4096

    // Q = x@Wq + bq  -> [B,H,S,dh]
    sgemm_128x64<<<dim3(M / 128, Dd / 64, 1), 256>>>(
        x, Dd, 0, Wq, Dd, 0, 0, bq, Qp, 0, 0, 1, Dd);
    // K = x@Wk + bk  -> [B,H,S,dh]
    sgemm_128x64<<<dim3(M / 128, Dd / 64, 1), 256>>>(
        x, Dd, 0, Wk, Dd, 0, 0, bk, Kp, 0, 0, 1, Dd);
    // V = x@Wv + bv  -> [B,S,dh]
    sgemm_128x64<<<dim3(M / 128, DHh / 64, 1), 256>>>(
        x, Dd, 0, Wv, DHh, 0, 0, bv, Vp, DHh, 0, 0, Dd);

    // fused QK + candidate screening (no logits materialization)
    qk_screen<<<dim3(Ss / 128, 1, Bb * Hh), 256, SCR_SMEM>>>(
        Qp, Kp, Cp, Np, Rp);

    // exact sparsemax + heads + avg from candidate lists
    sparse_final<<<Bb * Ss, 256>>>(Cp, Np, Rp, Qp, Kp, Vp, Hp, avg);

    // x_out = heads @ Wout + bout
    sgemm_128x64<<<dim3(M / 128, Dd / 64, 1), 256>>>(
        Hp, Dd, 0, Wout, Dd, 0, 0, bout, x_out, Dd, 0, 0, Dd);
}